// round 15
// baseline (speedup 1.0000x reference)
#include <cuda_runtime.h>
#include <cuda_bf16.h>
#include <cstdint>

#define K_DIM 512
#define N_DIM 512
#define BM 128
#define BN 256
#define M_MAX 65536

// ---------------- scratch (allocation-free) ----------------
// bf16 tiled+swizzled images. Sub-tile = 8KB = 128 rows x 64B (32 bf16 cols),
// byte (r,b) at r*64 + (b ^ ((r*8)&0x30)).
// x: sub-tile index = mtile*16 + c32; w: ntile*16 + c32 (ntile = 128 N rows).
__device__ float g_bq[N_DIM];
__device__ __align__(16) __nv_bfloat16 g_wqh[N_DIM * K_DIM];
__device__ __align__(16) __nv_bfloat16 g_xqh[(size_t)M_MAX * K_DIM];

// ---------------- helpers ----------------
__device__ __forceinline__ uint32_t smem_u32(const void* p) {
    uint32_t a;
    asm("{ .reg .u64 t; cvta.to.shared.u64 t, %1; cvt.u32.u64 %0, t; }" : "=r"(a) : "l"(p));
    return a;
}
__device__ __forceinline__ void cp_bulk(uint32_t dst, const void* src, uint32_t bytes, uint32_t mbar) {
    asm volatile("cp.async.bulk.shared::cluster.global.mbarrier::complete_tx::bytes [%0], [%1], %2, [%3];"
                 :: "r"(dst), "l"(src), "r"(bytes), "r"(mbar) : "memory");
}
#define MBARRIER_INIT(addr, cnt) \
    asm volatile("mbarrier.init.shared.b64 [%0], %1;" :: "r"(addr), "r"(cnt) : "memory")
#define MBARRIER_EXPECT_TX(addr, tx) \
    asm volatile("mbarrier.arrive.expect_tx.shared.b64 _, [%0], %1;" :: "r"(addr), "r"(tx) : "memory")
#define MBARRIER_WAIT_PARITY(addr, par) do {                                        \
    uint32_t _m = (addr), _p = (par), _d;                                           \
    asm volatile("{ .reg .pred p; mbarrier.try_wait.parity.acquire.cta.shared::cta.b64 p, [%1], %2; selp.b32 %0,1,0,p; }" \
        : "=r"(_d) : "r"(_m), "r"(_p) : "memory");                                  \
    if (!_d) {                                                                      \
        asm volatile("{ .reg .pred P1; WL_%=: mbarrier.try_wait.parity.acquire.cta.shared::cta.b64 P1, [%0], %1, 0x989680;" \
                     " @P1 bra.uni WD_%=; bra.uni WL_%=; WD_%=: }"                  \
            :: "r"(_m), "r"(_p) : "memory");                                        \
    } } while (0)

__device__ __forceinline__ void ldmatrix_x4(uint32_t* r, uint32_t addr) {
    asm volatile("ldmatrix.sync.aligned.m8n8.x4.shared.b16 {%0,%1,%2,%3}, [%4];"
                 : "=r"(r[0]), "=r"(r[1]), "=r"(r[2]), "=r"(r[3]) : "r"(addr));
}
__device__ __forceinline__ void mma_16816(float* d, const uint32_t* a, uint32_t b0, uint32_t b1) {
    asm volatile("mma.sync.aligned.m16n8k16.row.col.f32.bf16.bf16.f32 "
                 "{%0,%1,%2,%3}, {%4,%5,%6,%7}, {%8,%9}, {%0,%1,%2,%3};"
                 : "+f"(d[0]), "+f"(d[1]), "+f"(d[2]), "+f"(d[3])
                 : "r"(a[0]), "r"(a[1]), "r"(a[2]), "r"(a[3]), "r"(b0), "r"(b1));
}

// ---------------- fused prep: weight quant (blocks 0..511) + x convert ------
__global__ void prep_kernel(const float* __restrict__ weight,
                            const float* __restrict__ bias,
                            const float* __restrict__ scale_x,
                            const float* __restrict__ x,
                            float* __restrict__ scale_out_dst,
                            int write_scale, int n16) {
    if (blockIdx.x < N_DIM) {
        __shared__ float red[256];
        const int o = blockIdx.x;
        const float* wrow = weight + o * K_DIM;

        float m = 0.0f;
        for (int k = threadIdx.x; k < K_DIM; k += 256) m = fmaxf(m, fabsf(wrow[k]));
        red[threadIdx.x] = m;
        __syncthreads();
        for (int s = 128; s > 0; s >>= 1) {
            if (threadIdx.x < s) red[threadIdx.x] = fmaxf(red[threadIdx.x], red[threadIdx.x + s]);
            __syncthreads();
        }
        const float scale = fmaxf(red[0], 1e-8f) / 127.0f;
        const float inv_scale = 1.0f / scale;

        const int nt = o >> 7, rn = o & 127;
        const uint32_t rsw = (rn * 8) & 0x30;
        char* wq = (char*)g_wqh;
        for (int k = threadIdx.x; k < K_DIM; k += 256) {
            float q = rintf(wrow[k] * inv_scale);         // round-half-even == jnp.round
            q = fminf(fmaxf(q, -128.0f), 127.0f);
            const size_t off = ((size_t)(nt * 16 + (k >> 5)) << 13) + rn * 64
                             + ((2 * (k & 31)) ^ rsw);
            *(__nv_bfloat16*)(wq + off) = __float2bfloat16_rn(q);   // exact small int
        }
        if (threadIdx.x == 0) {
            const float so = scale * scale_x[0];
            float bq = rintf(bias[o] / so);
            bq = fminf(fmaxf(bq, -2147483520.0f), 2147483520.0f);
            g_bq[o] = bq;
            if (write_scale) scale_out_dst[o] = so;
        }
    } else {
        const int i = (blockIdx.x - N_DIM) * 256 + threadIdx.x;
        if (i >= n16) return;
        const int m = i >> 5, j16 = i & 31;               // row, 16-float group
        const float4* p = (const float4*)(x + (size_t)m * K_DIM + j16 * 16);
        float4 v0 = p[0], v1 = p[1], v2 = p[2], v3 = p[3];
        uint32_t q[8];
        asm("cvt.rn.bf16x2.f32 %0, %1, %2;" : "=r"(q[0]) : "f"(v0.y), "f"(v0.x));
        asm("cvt.rn.bf16x2.f32 %0, %1, %2;" : "=r"(q[1]) : "f"(v0.w), "f"(v0.z));
        asm("cvt.rn.bf16x2.f32 %0, %1, %2;" : "=r"(q[2]) : "f"(v1.y), "f"(v1.x));
        asm("cvt.rn.bf16x2.f32 %0, %1, %2;" : "=r"(q[3]) : "f"(v1.w), "f"(v1.z));
        asm("cvt.rn.bf16x2.f32 %0, %1, %2;" : "=r"(q[4]) : "f"(v2.y), "f"(v2.x));
        asm("cvt.rn.bf16x2.f32 %0, %1, %2;" : "=r"(q[5]) : "f"(v2.w), "f"(v2.z));
        asm("cvt.rn.bf16x2.f32 %0, %1, %2;" : "=r"(q[6]) : "f"(v3.y), "f"(v3.x));
        asm("cvt.rn.bf16x2.f32 %0, %1, %2;" : "=r"(q[7]) : "f"(v3.w), "f"(v3.z));
        const int c32 = j16 >> 1, half = j16 & 1;
        const int mt = m >> 7, r = m & 127;
        const uint32_t rsw = (r * 8) & 0x30;
        char* base = (char*)g_xqh + ((size_t)(mt * 16 + c32) << 13) + r * 64;
        *(uint4*)(base + ((half * 32)      ^ rsw)) = make_uint4(q[0], q[1], q[2], q[3]);
        *(uint4*)(base + ((half * 32 + 16) ^ rsw)) = make_uint4(q[4], q[5], q[6], q[7]);
    }
}

// ---------------- bf16 HMMA GEMM: 128x256 block, 64x64 warp tiles ------------
// 256 threads, 8 warps 2(M)x4(N). Chunk K=64: A 16KB + B 32KB = 48KB/stage,
// 3 stages. B smem layout per stage: [c32 sub][256 rows x 64B] (rows contiguous).
#define S_STAGE  49152
#define S_MBAR   147456
#define S_TOTAL  147584

__global__ __launch_bounds__(256, 1) void gemm_hmma(float* __restrict__ C) {
    extern __shared__ __align__(1024) char smem[];
    const uint32_t sb = smem_u32(smem);
    const int tid = threadIdx.x, lane = tid & 31, w = tid >> 5;
    const int wm = w & 1, wn = w >> 1;

    const char* srcA  = (const char*)g_xqh + ((size_t)blockIdx.y << 17);          // 128KB tile
    const char* srcB0 = (const char*)g_wqh + ((size_t)(blockIdx.x * 2)     << 17);
    const char* srcB1 = (const char*)g_wqh + ((size_t)(blockIdx.x * 2 + 1) << 17);

    // fragment lane addressing (64B rows, swizzle (row*8)&0x30)
    const uint32_t afr = wm * 64 + (lane & 15);
    const uint32_t afrx = (afr * 8) & 0x30;
    const uint32_t afkb = (lane >> 4) * 16;
    const uint32_t afbase = sb + afr * 64;
    const uint32_t bfr = wn * 64 + ((lane >> 4) << 3) + (lane & 7);   // [wn*64, wn*64+16)
    const uint32_t bfrx = (bfr * 8) & 0x30;
    const uint32_t bfkb = ((lane >> 3) & 1) * 16;
    const uint32_t bfbase = sb + 16384 + bfr * 64;                     // + stage + sub*16384

    if (tid == 0) {
        #pragma unroll
        for (int s = 0; s < 8; s++) MBARRIER_INIT(sb + S_MBAR + s * 8, 1);
        #pragma unroll
        for (int c = 0; c < 2; c++) {                      // prologue: chunks 0,1
            const uint32_t so = (uint32_t)c * S_STAGE;
            MBARRIER_EXPECT_TX(sb + S_MBAR + c * 8, 49152u);
            cp_bulk(sb + so, srcA + (size_t)c * 16384, 16384u, sb + S_MBAR + c * 8);
            #pragma unroll
            for (int s2 = 0; s2 < 2; s2++) {               // B: [sub][256 rows]
                cp_bulk(sb + so + 16384 + s2 * 16384,
                        srcB0 + (size_t)c * 16384 + s2 * 8192, 8192u, sb + S_MBAR + c * 8);
                cp_bulk(sb + so + 16384 + s2 * 16384 + 8192,
                        srcB1 + (size_t)c * 16384 + s2 * 8192, 8192u, sb + S_MBAR + c * 8);
            }
        }
    }
    __syncthreads();

    float acc[4][8][4] = {};
    int stg = 0;

    #pragma unroll 1
    for (int c = 0; c < 8; c++) {
        MBARRIER_WAIT_PARITY(sb + S_MBAR + c * 8, 0);
        __syncthreads();               // chunk c-1 fully read -> its stage reusable

        if (tid == 0 && c < 6) {
            const int cn = c + 2;
            int sn = stg + 2; if (sn >= 3) sn -= 3;
            const uint32_t so1 = (uint32_t)sn * S_STAGE;
            MBARRIER_EXPECT_TX(sb + S_MBAR + cn * 8, 49152u);
            cp_bulk(sb + so1, srcA + (size_t)cn * 16384, 16384u, sb + S_MBAR + cn * 8);
            #pragma unroll
            for (int s2 = 0; s2 < 2; s2++) {
                cp_bulk(sb + so1 + 16384 + s2 * 16384,
                        srcB0 + (size_t)cn * 16384 + s2 * 8192, 8192u, sb + S_MBAR + cn * 8);
                cp_bulk(sb + so1 + 16384 + s2 * 16384 + 8192,
                        srcB1 + (size_t)cn * 16384 + s2 * 8192, 8192u, sb + S_MBAR + cn * 8);
            }
        }

        const uint32_t so = (uint32_t)stg * S_STAGE;
        #pragma unroll
        for (int kk = 0; kk < 4; kk++) {                   // 4 x K16
            const uint32_t sub = (uint32_t)(kk >> 1);
            const uint32_t kb  = (uint32_t)(kk & 1) * 32;
            uint32_t af[4][4], bf[4][4];
            #pragma unroll
            for (int mi = 0; mi < 4; mi++)
                ldmatrix_x4(af[mi], afbase + so + sub * 8192 + mi * 1024 + ((kb + afkb) ^ afrx));
            #pragma unroll
            for (int pq = 0; pq < 4; pq++)
                ldmatrix_x4(bf[pq], bfbase + so + sub * 16384 + pq * 1024 + ((kb + bfkb) ^ bfrx));
            #pragma unroll
            for (int mi = 0; mi < 4; mi++)
                #pragma unroll
                for (int ni = 0; ni < 8; ni++)
                    mma_16816(acc[mi][ni], af[mi],
                              bf[ni >> 1][(ni & 1) * 2], bf[ni >> 1][(ni & 1) * 2 + 1]);
        }
        if (++stg == 3) stg = 0;
    }

    // ---------------- epilogue: +bias, float2 stores ----------------
    const int mrow = blockIdx.y * BM + wm * 64 + (lane >> 2);
    const int ncol = blockIdx.x * BN + wn * 64 + (lane & 3) * 2;
    #pragma unroll
    for (int ni = 0; ni < 8; ni++) {
        const float2 bq = *(const float2*)&g_bq[ncol + ni * 8];
        #pragma unroll
        for (int mi = 0; mi < 4; mi++) {
            const int rr = mrow + mi * 16;
            float2 v0 = make_float2(acc[mi][ni][0] + bq.x, acc[mi][ni][1] + bq.y);
            float2 v1 = make_float2(acc[mi][ni][2] + bq.x, acc[mi][ni][3] + bq.y);
            *(float2*)(C + (size_t)rr * N_DIM + ncol + ni * 8) = v0;
            *(float2*)(C + (size_t)(rr + 8) * N_DIM + ncol + ni * 8) = v1;
        }
    }
}

// ---------------- launch ----------------
extern "C" void kernel_launch(void* const* d_in, const int* in_sizes, int n_in,
                              void* d_out, int out_size) {
    const float* x_q     = (const float*)d_in[0];   // [M, 512]
    const float* weight  = (const float*)d_in[1];   // [512, 512]
    const float* bias    = (const float*)d_in[2];   // [512]
    const float* scale_x = (const float*)d_in[3];   // [1]
    float* out = (float*)d_out;

    const int M = in_sizes[0] / K_DIM;
    const long long need = (long long)M * N_DIM + N_DIM;
    const int write_scale = ((long long)out_size >= need) ? 1 : 0;

    const int n16 = M * K_DIM / 16;
    const int prep_blocks = N_DIM + (n16 + 255) / 256;
    prep_kernel<<<prep_blocks, 256>>>(weight, bias, scale_x, x_q,
                                      out + (size_t)M * N_DIM, write_scale, n16);

    cudaFuncSetAttribute(gemm_hmma, cudaFuncAttributeMaxDynamicSharedMemorySize, S_TOTAL);
    dim3 grid(N_DIM / BN, M / BM);
    gemm_hmma<<<grid, 256, S_TOTAL>>>(out);
}

// round 16
// speedup vs baseline: 1.1055x; 1.1055x over previous
#include <cuda_runtime.h>
#include <cuda_bf16.h>
#include <cstdint>

#define K_DIM 512
#define N_DIM 512
#define BM 128
#define BN 128
#define M_MAX 65536

// ---------------- scratch (allocation-free) ----------------
// bf16 tiled+swizzled images. Sub-tile = 8KB = 128 rows x 64B (32 bf16 cols),
// byte (r,b) at r*64 + (b ^ ((r*8)&0x30)).
// x: sub-tile index = mtile*16 + c32; w: ntile*16 + c32.
__device__ float g_bq[N_DIM];
__device__ __align__(16) __nv_bfloat16 g_wqh[N_DIM * K_DIM];
__device__ __align__(16) __nv_bfloat16 g_xqh[(size_t)M_MAX * K_DIM];

// ---------------- helpers ----------------
__device__ __forceinline__ uint32_t smem_u32(const void* p) {
    uint32_t a;
    asm("{ .reg .u64 t; cvta.to.shared.u64 t, %1; cvt.u32.u64 %0, t; }" : "=r"(a) : "l"(p));
    return a;
}
__device__ __forceinline__ void cp_bulk(uint32_t dst, const void* src, uint32_t bytes, uint32_t mbar) {
    asm volatile("cp.async.bulk.shared::cluster.global.mbarrier::complete_tx::bytes [%0], [%1], %2, [%3];"
                 :: "r"(dst), "l"(src), "r"(bytes), "r"(mbar) : "memory");
}
#define MBARRIER_INIT(addr, cnt) \
    asm volatile("mbarrier.init.shared.b64 [%0], %1;" :: "r"(addr), "r"(cnt) : "memory")
#define MBARRIER_EXPECT_TX(addr, tx) \
    asm volatile("mbarrier.arrive.expect_tx.shared.b64 _, [%0], %1;" :: "r"(addr), "r"(tx) : "memory")
#define MBARRIER_ARRIVE(addr) \
    asm volatile("mbarrier.arrive.shared.b64 _, [%0];" :: "r"(addr) : "memory")
#define MBARRIER_WAIT_PARITY(addr, par) do {                                        \
    uint32_t _m = (addr), _p = (par), _d;                                           \
    asm volatile("{ .reg .pred p; mbarrier.try_wait.parity.acquire.cta.shared::cta.b64 p, [%1], %2; selp.b32 %0,1,0,p; }" \
        : "=r"(_d) : "r"(_m), "r"(_p) : "memory");                                  \
    if (!_d) {                                                                      \
        asm volatile("{ .reg .pred P1; WL_%=: mbarrier.try_wait.parity.acquire.cta.shared::cta.b64 P1, [%0], %1, 0x989680;" \
                     " @P1 bra.uni WD_%=; bra.uni WL_%=; WD_%=: }"                  \
            :: "r"(_m), "r"(_p) : "memory");                                        \
    } } while (0)

__device__ __forceinline__ void ldmatrix_x4(uint32_t* r, uint32_t addr) {
    asm volatile("ldmatrix.sync.aligned.m8n8.x4.shared.b16 {%0,%1,%2,%3}, [%4];"
                 : "=r"(r[0]), "=r"(r[1]), "=r"(r[2]), "=r"(r[3]) : "r"(addr));
}
__device__ __forceinline__ void mma_16816(float* d, const uint32_t* a, uint32_t b0, uint32_t b1) {
    asm volatile("mma.sync.aligned.m16n8k16.row.col.f32.bf16.bf16.f32 "
                 "{%0,%1,%2,%3}, {%4,%5,%6,%7}, {%8,%9}, {%0,%1,%2,%3};"
                 : "+f"(d[0]), "+f"(d[1]), "+f"(d[2]), "+f"(d[3])
                 : "r"(a[0]), "r"(a[1]), "r"(a[2]), "r"(a[3]), "r"(b0), "r"(b1));
}

// ---------------- fused prep: weight quant (blocks 0..511) + x convert ------
__global__ void prep_kernel(const float* __restrict__ weight,
                            const float* __restrict__ bias,
                            const float* __restrict__ scale_x,
                            const float* __restrict__ x,
                            float* __restrict__ scale_out_dst,
                            int write_scale, int n16) {
    if (blockIdx.x < N_DIM) {
        __shared__ float red[256];
        const int o = blockIdx.x;
        const float* wrow = weight + o * K_DIM;

        float m = 0.0f;
        for (int k = threadIdx.x; k < K_DIM; k += 256) m = fmaxf(m, fabsf(wrow[k]));
        red[threadIdx.x] = m;
        __syncthreads();
        for (int s = 128; s > 0; s >>= 1) {
            if (threadIdx.x < s) red[threadIdx.x] = fmaxf(red[threadIdx.x], red[threadIdx.x + s]);
            __syncthreads();
        }
        const float scale = fmaxf(red[0], 1e-8f) / 127.0f;
        const float inv_scale = 1.0f / scale;

        const int nt = o >> 7, rn = o & 127;
        const uint32_t rsw = (rn * 8) & 0x30;
        char* wq = (char*)g_wqh;
        for (int k = threadIdx.x; k < K_DIM; k += 256) {
            float q = rintf(wrow[k] * inv_scale);         // round-half-even == jnp.round
            q = fminf(fmaxf(q, -128.0f), 127.0f);
            const size_t off = ((size_t)(nt * 16 + (k >> 5)) << 13) + rn * 64
                             + ((2 * (k & 31)) ^ rsw);
            *(__nv_bfloat16*)(wq + off) = __float2bfloat16_rn(q);   // exact small int
        }
        if (threadIdx.x == 0) {
            const float so = scale * scale_x[0];
            float bq = rintf(bias[o] / so);
            bq = fminf(fmaxf(bq, -2147483520.0f), 2147483520.0f);
            g_bq[o] = bq;
            if (write_scale) scale_out_dst[o] = so;
        }
    } else {
        const int i = (blockIdx.x - N_DIM) * 256 + threadIdx.x;
        if (i >= n16) return;
        const int m = i >> 5, j16 = i & 31;               // row, 16-float group
        const float4* p = (const float4*)(x + (size_t)m * K_DIM + j16 * 16);
        float4 v0 = p[0], v1 = p[1], v2 = p[2], v3 = p[3];
        uint32_t q[8];
        asm("cvt.rn.bf16x2.f32 %0, %1, %2;" : "=r"(q[0]) : "f"(v0.y), "f"(v0.x));
        asm("cvt.rn.bf16x2.f32 %0, %1, %2;" : "=r"(q[1]) : "f"(v0.w), "f"(v0.z));
        asm("cvt.rn.bf16x2.f32 %0, %1, %2;" : "=r"(q[2]) : "f"(v1.y), "f"(v1.x));
        asm("cvt.rn.bf16x2.f32 %0, %1, %2;" : "=r"(q[3]) : "f"(v1.w), "f"(v1.z));
        asm("cvt.rn.bf16x2.f32 %0, %1, %2;" : "=r"(q[4]) : "f"(v2.y), "f"(v2.x));
        asm("cvt.rn.bf16x2.f32 %0, %1, %2;" : "=r"(q[5]) : "f"(v2.w), "f"(v2.z));
        asm("cvt.rn.bf16x2.f32 %0, %1, %2;" : "=r"(q[6]) : "f"(v3.y), "f"(v3.x));
        asm("cvt.rn.bf16x2.f32 %0, %1, %2;" : "=r"(q[7]) : "f"(v3.w), "f"(v3.z));
        const int c32 = j16 >> 1, half = j16 & 1;
        const int mt = m >> 7, r = m & 127;
        const uint32_t rsw = (r * 8) & 0x30;
        char* base = (char*)g_xqh + ((size_t)(mt * 16 + c32) << 13) + r * 64;
        *(uint4*)(base + ((half * 32)      ^ rsw)) = make_uint4(q[0], q[1], q[2], q[3]);
        *(uint4*)(base + ((half * 32 + 16) ^ rsw)) = make_uint4(q[4], q[5], q[6], q[7]);
    }
}

// ---------------- bf16 HMMA GEMM: warp-specialized producer/consumer --------
// 288 threads: 8 consumer warps 2(M)x4(N) (warp tile 64x32) + 1 producer warp.
// 3 stages x 32KB (A 16KB + B 16KB); full[s] = tx mbarrier, empty[s] = 8-arrive.
#define S_STAGE  32768
#define S_MBAR   98304          // full[0..2] @ +0,+8,+16 ; empty[0..2] @ +24,+32,+40
#define S_TOTAL  98432

__global__ __launch_bounds__(288, 2) void gemm_hmma(float* __restrict__ C) {
    extern __shared__ __align__(1024) char smem[];
    const uint32_t sb = smem_u32(smem);
    const int tid = threadIdx.x, lane = tid & 31, w = tid >> 5;

    const char* srcA = (const char*)g_xqh + ((size_t)blockIdx.y << 17);   // 128KB tile
    const char* srcB = (const char*)g_wqh + ((size_t)blockIdx.x << 17);

    if (tid == 0) {
        #pragma unroll
        for (int s = 0; s < 3; s++) {
            MBARRIER_INIT(sb + S_MBAR + s * 8, 1);        // full: tx-based
            MBARRIER_INIT(sb + S_MBAR + 24 + s * 8, 8);   // empty: 8 consumer warps
        }
    }
    __syncthreads();

    if (w == 8) {
        // ---------------- producer warp: one thread issues all 8 chunks ------
        if (lane == 0) {
            #pragma unroll 1
            for (int c = 0; c < 8; c++) {
                int s = c; if (s >= 6) s -= 6; else if (s >= 3) s -= 3;   // c % 3
                const uint32_t full  = sb + S_MBAR + s * 8;
                const uint32_t empty = sb + S_MBAR + 24 + s * 8;
                if (c >= 3) MBARRIER_WAIT_PARITY(empty, ((c - 3) / 3) & 1);
                const uint32_t so = (uint32_t)s * S_STAGE;
                MBARRIER_EXPECT_TX(full, 32768u);
                cp_bulk(sb + so,         srcA + (size_t)c * 16384, 16384u, full);
                cp_bulk(sb + so + 16384, srcB + (size_t)c * 16384, 16384u, full);
            }
        }
        return;
    }

    // ---------------- consumer warps ----------------
    const int wm = w & 1, wn = w >> 1;
    const uint32_t afr = wm * 64 + (lane & 15);
    const uint32_t afrx = (afr * 8) & 0x30;
    const uint32_t afkb = (lane >> 4) * 16;
    const uint32_t afbase = sb + afr * 64;
    const uint32_t bfr = wn * 32 + ((lane >> 4) << 3) + (lane & 7);
    const uint32_t bfrx = (bfr * 8) & 0x30;
    const uint32_t bfkb = ((lane >> 3) & 1) * 16;
    const uint32_t bfbase = sb + 16384 + bfr * 64;

    float acc[4][4][4] = {};

    #pragma unroll 1
    for (int c = 0; c < 8; c++) {
        int s = c; if (s >= 6) s -= 6; else if (s >= 3) s -= 3;           // c % 3
        MBARRIER_WAIT_PARITY(sb + S_MBAR + s * 8, (c / 3) & 1);

        const uint32_t so = (uint32_t)s * S_STAGE;
        #pragma unroll
        for (int kk = 0; kk < 4; kk++) {                  // 4 x K16 per chunk
            const uint32_t sub = (uint32_t)(kk >> 1) * 8192;
            const uint32_t kb  = (uint32_t)(kk & 1) * 32;
            uint32_t af[4][4], bf[2][4];
            #pragma unroll
            for (int mi = 0; mi < 4; mi++)
                ldmatrix_x4(af[mi], afbase + so + sub + mi * 1024 + ((kb + afkb) ^ afrx));
            #pragma unroll
            for (int pq = 0; pq < 2; pq++)
                ldmatrix_x4(bf[pq], bfbase + so + sub + pq * 1024 + ((kb + bfkb) ^ bfrx));
            #pragma unroll
            for (int mi = 0; mi < 4; mi++)
                #pragma unroll
                for (int ni = 0; ni < 4; ni++)
                    mma_16816(acc[mi][ni], af[mi],
                              bf[ni >> 1][(ni & 1) * 2], bf[ni >> 1][(ni & 1) * 2 + 1]);
        }
        if (lane == 0) MBARRIER_ARRIVE(sb + S_MBAR + 24 + s * 8);
    }

    // ---------------- epilogue: +bias, float2 stores ----------------
    const int mrow = blockIdx.y * BM + wm * 64 + (lane >> 2);
    const int ncol = blockIdx.x * BN + wn * 32 + (lane & 3) * 2;
    #pragma unroll
    for (int ni = 0; ni < 4; ni++) {
        const float2 bq = *(const float2*)&g_bq[ncol + ni * 8];
        #pragma unroll
        for (int mi = 0; mi < 4; mi++) {
            const int rr = mrow + mi * 16;
            float2 v0 = make_float2(acc[mi][ni][0] + bq.x, acc[mi][ni][1] + bq.y);
            float2 v1 = make_float2(acc[mi][ni][2] + bq.x, acc[mi][ni][3] + bq.y);
            *(float2*)(C + (size_t)rr * N_DIM + ncol + ni * 8) = v0;
            *(float2*)(C + (size_t)(rr + 8) * N_DIM + ncol + ni * 8) = v1;
        }
    }
}

// ---------------- launch ----------------
extern "C" void kernel_launch(void* const* d_in, const int* in_sizes, int n_in,
                              void* d_out, int out_size) {
    const float* x_q     = (const float*)d_in[0];   // [M, 512]
    const float* weight  = (const float*)d_in[1];   // [512, 512]
    const float* bias    = (const float*)d_in[2];   // [512]
    const float* scale_x = (const float*)d_in[3];   // [1]
    float* out = (float*)d_out;

    const int M = in_sizes[0] / K_DIM;
    const long long need = (long long)M * N_DIM + N_DIM;
    const int write_scale = ((long long)out_size >= need) ? 1 : 0;

    const int n16 = M * K_DIM / 16;
    const int prep_blocks = N_DIM + (n16 + 255) / 256;
    prep_kernel<<<prep_blocks, 256>>>(weight, bias, scale_x, x_q,
                                      out + (size_t)M * N_DIM, write_scale, n16);

    cudaFuncSetAttribute(gemm_hmma, cudaFuncAttributeMaxDynamicSharedMemorySize, S_TOTAL);
    dim3 grid(N_DIM / BN, M / BM);
    gemm_hmma<<<grid, 288, S_TOTAL>>>(out);
}